// round 16
// baseline (speedup 1.0000x reference)
#include <cuda_runtime.h>
#include <cuda_bf16.h>
#include <cuda_fp16.h>
#include <math.h>
#include <stdint.h>

#define BB     16
#define LSEQ   1024
#define DDIM   768
#define HDIM   256
#define NHEAD  4
#define OUTD   768
#define BLROWS (BB*LSEQ)          // 16384
#define NJC    13                 // early-stop chunk count for certification

// ---------------- scratch (device globals; no allocation) ----------------
__device__ float g_h[(size_t)NHEAD * BLROWS * HDIM];              // fp32 h
__device__ __nv_bfloat16 g_hb[(size_t)NHEAD * BLROWS * HDIM];     // bf16 h
__device__ __nv_bfloat16 g_tb[(size_t)NHEAD * BLROWS * HDIM];     // bf16 t
__device__ __nv_bfloat16 g_adjwT[(size_t)NHEAD * HDIM * HDIM];    // adjw^T bf16
__device__ __half g_xh[(size_t)BLROWS * DDIM];                    // fp16 x
__device__ __half g_WTh[(size_t)NHEAD * HDIM * DDIM];             // fp16 Wfc^T
__device__ float g_esrc[NHEAD * BLROWS];
__device__ float g_edst[NHEAD * BLROWS];
__device__ float g_partial[NHEAD * BB * 16 * HDIM];               // base colsums (64-row blocks)
__device__ float g_adj[NHEAD * BB * 8 * HDIM];                    // fallback adjustments (from attn)

// ---------------- helpers ----------------
__device__ __forceinline__ float wredsum(float v) {
    #pragma unroll
    for (int o = 16; o; o >>= 1) v += __shfl_xor_sync(0xffffffffu, v, o);
    return v;
}
__device__ __forceinline__ float sigf(float x) {
    if (x >= 0.f) { float z = expf(-x); return 1.f / (1.f + z); }
    float z = expf(x); return z / (1.f + z);
}
__device__ __forceinline__ void mma16816bf(float c[4], const unsigned a[4], const unsigned b[2]) {
    asm volatile("mma.sync.aligned.m16n8k16.row.col.f32.bf16.bf16.f32 "
        "{%0,%1,%2,%3}, {%4,%5,%6,%7}, {%8,%9}, {%0,%1,%2,%3};"
        : "+f"(c[0]), "+f"(c[1]), "+f"(c[2]), "+f"(c[3])
        : "r"(a[0]), "r"(a[1]), "r"(a[2]), "r"(a[3]), "r"(b[0]), "r"(b[1]));
}
__device__ __forceinline__ void mma16816f(float c[4], const unsigned a[4], const unsigned b[2]) {
    asm volatile("mma.sync.aligned.m16n8k16.row.col.f32.f16.f16.f32 "
        "{%0,%1,%2,%3}, {%4,%5,%6,%7}, {%8,%9}, {%0,%1,%2,%3};"
        : "+f"(c[0]), "+f"(c[1]), "+f"(c[2]), "+f"(c[3])
        : "r"(a[0]), "r"(a[1]), "r"(a[2]), "r"(a[3]), "r"(b[0]), "r"(b[1]));
}
__device__ __forceinline__ void ldsm4(unsigned r[4], unsigned addr) {
    asm volatile("ldmatrix.sync.aligned.m8n8.x4.shared.b16 {%0,%1,%2,%3}, [%4];"
        : "=r"(r[0]), "=r"(r[1]), "=r"(r[2]), "=r"(r[3]) : "r"(addr));
}
__device__ __forceinline__ unsigned sptr(const void* p) {
    return (unsigned)__cvta_generic_to_shared(p);
}
__device__ __forceinline__ void cpa16(unsigned dst, const void* src) {
    asm volatile("cp.async.cg.shared.global [%0], [%1], 16;" :: "r"(dst), "l"(src));
}
__device__ __forceinline__ void cpcommit() { asm volatile("cp.async.commit_group;"); }
template<int N> __device__ __forceinline__ void cpwait() {
    asm volatile("cp.async.wait_group %0;" :: "n"(N));
}

// ---------------- prep: x -> fp16 ----------------
__global__ void split_x_kernel(const float* __restrict__ x)
{
    long i = (long)blockIdx.x * 1024 + threadIdx.x * 4;
    float4 v = *(const float4*)(x + i);
    *(__half2*)&g_xh[i]     = __floats2half2_rn(v.x, v.y);
    *(__half2*)&g_xh[i + 2] = __floats2half2_rn(v.z, v.w);
}

// ---------------- prep: Wfc^T fp16, tiled transpose ----------------
__global__ void split_W_kernel(const float* __restrict__ Wfc)
{
    __shared__ float t[32][33];
    int d0 = blockIdx.x * 32, e0 = blockIdx.y * 32, n = blockIdx.z;
    int tx = threadIdx.x, ty = threadIdx.y;
    #pragma unroll
    for (int r = 0; r < 4; ++r) {
        int d = d0 + ty * 4 + r;
        t[ty * 4 + r][tx] = Wfc[((long)n * DDIM + d) * HDIM + e0 + tx];
    }
    __syncthreads();
    #pragma unroll
    for (int r = 0; r < 4; ++r) {
        int e = e0 + ty * 4 + r;
        g_WTh[((long)n * HDIM + e) * DDIM + d0 + tx] = __float2half(t[tx][ty * 4 + r]);
    }
}

// ---------------- prep: adjw^T bf16, tiled transpose ----------------
__global__ void adjwT_kernel(const float* __restrict__ adjw)
{
    __shared__ float t[32][33];
    int d0 = blockIdx.x * 32, e0 = blockIdx.y * 32, n = blockIdx.z;
    int tx = threadIdx.x, ty = threadIdx.y;
    #pragma unroll
    for (int r = 0; r < 4; ++r) {
        int d = d0 + ty * 4 + r;
        t[ty * 4 + r][tx] = adjw[((long)n * HDIM + d) * HDIM + e0 + tx];
    }
    __syncthreads();
    #pragma unroll
    for (int r = 0; r < 4; ++r) {
        int e = e0 + ty * 4 + r;
        g_adjwT[((long)n * HDIM + e) * HDIM + d0 + tx] = __float2bfloat16(t[tx][ty * 4 + r]);
    }
}

// ---------------- fused stage 1: h = LN(x @ Wfc + bfc) ----------------
// grid (256 mblk64, NHEAD); block 256 = 8 warps (2x4); warp tile 32x64; 2 CTAs/SM
__global__ void __launch_bounds__(256, 2) fc_ln_kernel(
    const float* __restrict__ bfc, const float* __restrict__ lng,
    const float* __restrict__ lnb, const float* __restrict__ Watt)
{
    extern __shared__ char smraw[];
    __half* sA = (__half*)smraw;                       // 3 * 64*40
    __half* sB = sA + 3 * 64 * 40;                     // 3 * 256*40
    // epilogue overlay (mainloop smem dead): tiny stat buffers
    float* rs     = (float*)smraw;                     // 64*4 row-sum partials
    float* rq     = rs + 256;                          // 64*4 row-sumsq partials
    float* esb    = rq + 256;                          // 64*4
    float* edb    = esb + 256;                         // 64*4
    float* colbuf = edb + 256;                         // 2*256

    int mblk = blockIdx.x, head = blockIdx.y;
    int tid = threadIdx.x, lane = tid & 31, w = tid >> 5;
    int wr = w >> 2, wc = w & 3;        // 2x4 warp grid

    const __half* Ag = g_xh + (long)mblk * 64 * DDIM;
    const __half* Bg = g_WTh + (long)head * HDIM * DDIM;

    float c[2][8][4];
    #pragma unroll
    for (int i = 0; i < 2; ++i)
        #pragma unroll
        for (int j = 0; j < 8; ++j)
            #pragma unroll
            for (int q = 0; q < 4; ++q) c[i][j][q] = 0.f;

    int aRow = wr * 32 + (lane & 7) + ((lane >> 3) & 1) * 8;
    int aK   = (lane >> 4) * 8;
    int bRow = wc * 64 + (lane & 7) + ((lane >> 4)) * 8;
    int bK   = ((lane >> 3) & 1) * 8;
    unsigned aAbase[3], bAbase[3];
    #pragma unroll
    for (int bb2 = 0; bb2 < 3; ++bb2) {
        aAbase[bb2] = sptr(sA + bb2 * 64 * 40) + ((aRow * 40 + aK) << 1);
        bAbase[bb2] = sptr(sB + bb2 * 256 * 40) + ((bRow * 40 + bK) << 1);
    }

    auto loadChunk = [&](int buf, int k0) {
        {   // A: 64 rows x 4 segs = 256 float4s; one per thread
            int row = tid >> 2, part = tid & 3;
            cpa16(sptr(sA + buf * 64 * 40 + row * 40 + part * 8),
                  &Ag[(long)row * DDIM + k0 + part * 8]);
        }
        #pragma unroll
        for (int q = 0; q < 4; ++q) {   // B: 256 rows x 4 segs = 1024 float4s
            int idx = tid + q * 256;
            int row = idx >> 2, part = idx & 3;
            cpa16(sptr(sB + buf * 256 * 40 + row * 40 + part * 8),
                  &Bg[(long)row * DDIM + k0 + part * 8]);
        }
        cpcommit();
    };

    loadChunk(0, 0);
    loadChunk(1, 32);
    int buf = 0;
    for (int kc = 0; kc < 24; ++kc) {
        cpwait<1>();
        __syncthreads();
        if (kc + 2 < 24) loadChunk((buf + 2) % 3, (kc + 2) * 32);
        #pragma unroll
        for (int ks = 0; ks < 32; ks += 16) {
            unsigned ah[2][4], bh[4][4];
            #pragma unroll
            for (int mt = 0; mt < 2; ++mt)
                ldsm4(ah[mt], aAbase[buf] + ((mt * 16 * 40 + ks) << 1));
            #pragma unroll
            for (int p = 0; p < 4; ++p)
                ldsm4(bh[p], bAbase[buf] + ((p * 16 * 40 + ks) << 1));
            #pragma unroll
            for (int mt = 0; mt < 2; ++mt)
                #pragma unroll
                for (int nt = 0; nt < 8; ++nt)
                    mma16816f(c[mt][nt], ah[mt], &bh[nt >> 1][(nt & 1) * 2]);
        }
        buf = (buf + 1) % 3;
    }
    __syncthreads();   // all warps done with mainloop smem; overlay stats

    // ---- bias add (registers) ----
    const float* bias = bfc + head * HDIM;
    #pragma unroll
    for (int mt = 0; mt < 2; ++mt)
        #pragma unroll
        for (int nt = 0; nt < 8; ++nt) {
            int col = wc * 64 + nt * 8 + (lane & 3) * 2;
            float b0 = bias[col], b1 = bias[col + 1];
            c[mt][nt][0] += b0; c[mt][nt][1] += b1;
            c[mt][nt][2] += b0; c[mt][nt][3] += b1;
        }

    // thread's 4 rows: ri -> row = wr*32 + (ri>>1)*16 + (ri&1)*8 + (lane>>2)
    int rowbase = wr * 32 + (lane >> 2);
    int myrow[4];
    #pragma unroll
    for (int ri = 0; ri < 4; ++ri) myrow[ri] = rowbase + (ri >> 1) * 16 + (ri & 1) * 8;

    // ---- pass 1: row sums ----
    {
        float srow[4] = {0.f, 0.f, 0.f, 0.f};
        #pragma unroll
        for (int mt = 0; mt < 2; ++mt)
            #pragma unroll
            for (int nt = 0; nt < 8; ++nt) {
                srow[mt * 2 + 0] += c[mt][nt][0] + c[mt][nt][1];
                srow[mt * 2 + 1] += c[mt][nt][2] + c[mt][nt][3];
            }
        #pragma unroll
        for (int ri = 0; ri < 4; ++ri) {
            srow[ri] += __shfl_xor_sync(0xffffffffu, srow[ri], 1);
            srow[ri] += __shfl_xor_sync(0xffffffffu, srow[ri], 2);
        }
        if ((lane & 3) == 0) {
            #pragma unroll
            for (int ri = 0; ri < 4; ++ri) rs[myrow[ri] * 4 + wc] = srow[ri];
        }
    }
    __syncthreads();
    float mu[4];
    #pragma unroll
    for (int ri = 0; ri < 4; ++ri)
        mu[ri] = (rs[myrow[ri] * 4 + 0] + rs[myrow[ri] * 4 + 1] +
                  rs[myrow[ri] * 4 + 2] + rs[myrow[ri] * 4 + 3]) * (1.f / 256.f);

    // ---- pass 2: row sumsq of (v - mu) ----
    {
        float qrow[4] = {0.f, 0.f, 0.f, 0.f};
        #pragma unroll
        for (int mt = 0; mt < 2; ++mt)
            #pragma unroll
            for (int nt = 0; nt < 8; ++nt) {
                float d0 = c[mt][nt][0] - mu[mt * 2], d1 = c[mt][nt][1] - mu[mt * 2];
                float d2 = c[mt][nt][2] - mu[mt * 2 + 1], d3 = c[mt][nt][3] - mu[mt * 2 + 1];
                qrow[mt * 2 + 0] += d0 * d0 + d1 * d1;
                qrow[mt * 2 + 1] += d2 * d2 + d3 * d3;
            }
        #pragma unroll
        for (int ri = 0; ri < 4; ++ri) {
            qrow[ri] += __shfl_xor_sync(0xffffffffu, qrow[ri], 1);
            qrow[ri] += __shfl_xor_sync(0xffffffffu, qrow[ri], 2);
        }
        if ((lane & 3) == 0) {
            #pragma unroll
            for (int ri = 0; ri < 4; ++ri) rq[myrow[ri] * 4 + wc] = qrow[ri];
        }
    }
    __syncthreads();
    float rstd[4];
    #pragma unroll
    for (int ri = 0; ri < 4; ++ri) {
        float s2 = rq[myrow[ri] * 4 + 0] + rq[myrow[ri] * 4 + 1] +
                   rq[myrow[ri] * 4 + 2] + rq[myrow[ri] * 4 + 3];
        rstd[ri] = rsqrtf(s2 * (1.f / 256.f) + 1e-5f);
    }

    // ---- normalize, write h/hb, accumulate dots + colsums ----
    const float* gzp = lng + head * HDIM;
    const float* bzp = lnb + head * HDIM;
    const float* wsp = Watt + head * 2 * HDIM;
    const float* wdp = wsp + HDIM;
    long growbase = (long)head * BLROWS + (long)mblk * 64;

    float a1[4] = {0.f, 0.f, 0.f, 0.f}, a2[4] = {0.f, 0.f, 0.f, 0.f};
    float csum[16];
    #pragma unroll
    for (int q = 0; q < 16; ++q) csum[q] = 0.f;

    #pragma unroll
    for (int mt = 0; mt < 2; ++mt)
        #pragma unroll
        for (int nt = 0; nt < 8; ++nt) {
            int col = wc * 64 + nt * 8 + (lane & 3) * 2;
            float gz0 = gzp[col], gz1 = gzp[col + 1];
            float bz0 = bzp[col], bz1 = bzp[col + 1];
            float ws0 = wsp[col], ws1 = wsp[col + 1];
            float wd0 = wdp[col], wd1 = wdp[col + 1];
            int riA = mt * 2, riB = mt * 2 + 1;
            float o0 = (c[mt][nt][0] - mu[riA]) * rstd[riA] * gz0 + bz0;
            float o1 = (c[mt][nt][1] - mu[riA]) * rstd[riA] * gz1 + bz1;
            float o2 = (c[mt][nt][2] - mu[riB]) * rstd[riB] * gz0 + bz0;
            float o3 = (c[mt][nt][3] - mu[riB]) * rstd[riB] * gz1 + bz1;

            long rA = growbase + myrow[riA];
            long rB = growbase + myrow[riB];
            *(float2*)&g_h[rA * HDIM + col] = make_float2(o0, o1);
            *(float2*)&g_h[rB * HDIM + col] = make_float2(o2, o3);
            *(__nv_bfloat162*)&g_hb[rA * HDIM + col] = __floats2bfloat162_rn(o0, o1);
            *(__nv_bfloat162*)&g_hb[rB * HDIM + col] = __floats2bfloat162_rn(o2, o3);

            a1[riA] = fmaf(o0, ws0, fmaf(o1, ws1, a1[riA]));
            a2[riA] = fmaf(o0, wd0, fmaf(o1, wd1, a2[riA]));
            a1[riB] = fmaf(o2, ws0, fmaf(o3, ws1, a1[riB]));
            a2[riB] = fmaf(o2, wd0, fmaf(o3, wd1, a2[riB]));

            csum[nt * 2 + 0] += o0 + o2;
            csum[nt * 2 + 1] += o1 + o3;
        }

    // dots: reduce over quad lanes, stash partials per wc
    #pragma unroll
    for (int ri = 0; ri < 4; ++ri) {
        a1[ri] += __shfl_xor_sync(0xffffffffu, a1[ri], 1);
        a1[ri] += __shfl_xor_sync(0xffffffffu, a1[ri], 2);
        a2[ri] += __shfl_xor_sync(0xffffffffu, a2[ri], 1);
        a2[ri] += __shfl_xor_sync(0xffffffffu, a2[ri], 2);
    }
    if ((lane & 3) == 0) {
        #pragma unroll
        for (int ri = 0; ri < 4; ++ri) {
            esb[myrow[ri] * 4 + wc] = a1[ri];
            edb[myrow[ri] * 4 + wc] = a2[ri];
        }
    }

    // colsums: reduce over the 8 row-lanes (same cols), stash per wr
    #pragma unroll
    for (int q = 0; q < 16; ++q) {
        csum[q] += __shfl_xor_sync(0xffffffffu, csum[q], 4);
        csum[q] += __shfl_xor_sync(0xffffffffu, csum[q], 8);
        csum[q] += __shfl_xor_sync(0xffffffffu, csum[q], 16);
    }
    if (lane < 4) {
        #pragma unroll
        for (int nt = 0; nt < 8; ++nt) {
            int col = wc * 64 + nt * 8 + lane * 2;
            colbuf[wr * 256 + col]     = csum[nt * 2 + 0];
            colbuf[wr * 256 + col + 1] = csum[nt * 2 + 1];
        }
    }
    __syncthreads();

    if (tid < 64) {
        long grow = growbase + tid;
        g_esrc[grow] = esb[tid * 4 + 0] + esb[tid * 4 + 1] + esb[tid * 4 + 2] + esb[tid * 4 + 3];
        g_edst[grow] = edb[tid * 4 + 0] + edb[tid * 4 + 1] + edb[tid * 4 + 2] + edb[tid * 4 + 3];
    }
    {
        float s = colbuf[tid] + colbuf[256 + tid];
        int b = mblk >> 4, slot = mblk & 15;
        g_partial[((long)(head * 16 + b) * 16 + slot) * 256 + tid] = s;
    }
}

// ---------------- tb = hb @ adjw (bf16 tensor, pipelined, smem overlay) ----
__global__ void __launch_bounds__(256, 2) tb_gemm_kernel()
{
    extern __shared__ char smraw[];
    __nv_bfloat16* sReg = (__nv_bfloat16*)smraw;     // 128*264
    __nv_bfloat16* sBuf[2] = { sReg, sReg + 64 * 264 };

    int mb = blockIdx.x, n = blockIdx.y;
    int tid = threadIdx.x, lane = tid & 31, w = tid >> 5;
    int gr = lane >> 2, qp = lane & 3;
    long rbase = (long)n * BLROWS + (long)mb * 128;
    const __nv_bfloat16* asrc = g_hb + rbase * HDIM;

    for (int idx = tid; idx < 128 * 32; idx += 256) {
        int r = idx >> 5, k8 = idx & 31;
        *(float4*)&sReg[r * 264 + k8 * 8] = *(const float4*)&asrc[(long)r * HDIM + k8 * 8];
    }
    __syncthreads();

    unsigned Afrag[16][4];
    {
        int aRow = w * 16 + (lane & 7) + ((lane >> 3) & 1) * 8;
        int aK = (lane >> 4) * 8;
        unsigned aA = sptr(sReg) + ((aRow * 264 + aK) << 1);
        #pragma unroll
        for (int kt = 0; kt < 16; ++kt) ldsm4(Afrag[kt], aA + ((kt * 16) << 1));
    }
    __syncthreads();

    auto loadB = [&](int buf, int ec) {
        const __nv_bfloat16* bsrc = g_adjwT + ((long)n * HDIM + ec * 64) * HDIM;
        #pragma unroll
        for (int q = 0; q < 8; ++q) {
            int idx = tid + q * 256;
            int r = idx >> 5, k8 = idx & 31;
            cpa16(sptr(&sBuf[buf][r * 264 + k8 * 8]), &bsrc[(long)r * HDIM + k8 * 8]);
        }
        cpcommit();
    };

    int bRowBase = (lane & 7) + ((lane >> 4)) * 8;
    int bK = ((lane >> 3) & 1) * 8;

    __nv_bfloat16* outp = g_tb + rbase * HDIM;
    loadB(0, 0);
    for (int ec = 0; ec < 4; ++ec) {
        cpwait<0>();
        __syncthreads();
        if (ec + 1 < 4) loadB((ec + 1) & 1, ec + 1);
        unsigned bA0 = sptr(sBuf[ec & 1]) + ((bRowBase * 264 + bK) << 1);
        #pragma unroll
        for (int ntp = 0; ntp < 4; ++ntp) {
            float c0[4] = {0.f, 0.f, 0.f, 0.f};
            float c1[4] = {0.f, 0.f, 0.f, 0.f};
            unsigned ba = bA0 + ((ntp * 16 * 264) << 1);
            #pragma unroll
            for (int kt = 0; kt < 16; ++kt) {
                unsigned bf[4];
                ldsm4(bf, ba + ((kt * 16) << 1));
                mma16816bf(c0, Afrag[kt], &bf[0]);
                mma16816bf(c1, Afrag[kt], &bf[2]);
            }
            int row = w * 16 + gr;
            int col = ec * 64 + ntp * 16 + qp * 2;
            *(__nv_bfloat162*)&outp[(long)row * HDIM + col] = __floats2bfloat162_rn(c0[0], c0[1]);
            *(__nv_bfloat162*)&outp[(long)(row + 8) * HDIM + col] = __floats2bfloat162_rn(c0[2], c0[3]);
            *(__nv_bfloat162*)&outp[(long)row * HDIM + col + 8] = __floats2bfloat162_rn(c1[0], c1[1]);
            *(__nv_bfloat162*)&outp[(long)(row + 8) * HDIM + col + 8] = __floats2bfloat162_rn(c1[2], c1[3]);
        }
    }
}

// ---------------- attention: tensor-core counting + exact fallback ------
#define TH_HI 33.4f
__global__ void __launch_bounds__(256, 2) attn_count_kernel(
    const float* __restrict__ adjw, const float* __restrict__ batt)
{
    extern __shared__ char smraw[];
    __nv_bfloat16* sReg = (__nv_bfloat16*)smraw;     // 128*264 overlay region
    __nv_bfloat16* sBuf[2] = { sReg, sReg + 64 * 264 };
    float* sCol = (float*)(sReg + 128 * 264);        // 256
    int*   sCnt = (int*)(sCol + 256);                // 128

    int mb = blockIdx.x, b = blockIdx.y, n = blockIdx.z;
    int tid = threadIdx.x, lane = tid & 31, w = tid >> 5;
    int gr = lane >> 2;
    long nb = (long)(n * 16 + b);
    long base = nb * LSEQ * HDIM;
    int r0 = mb * 128;
    int erow0 = n * BLROWS + b * LSEQ;
    const __nv_bfloat16* hbp = g_hb + base;
    const __nv_bfloat16* tbp = g_tb + base + (long)r0 * HDIM;

    for (int idx = tid; idx < 128 * 32; idx += 256) {
        int r = idx >> 5, k8 = idx & 31;
        *(float4*)&sReg[r * 264 + k8 * 8] = *(const float4*)&tbp[(long)r * HDIM + k8 * 8];
    }
    __syncthreads();

    unsigned Afrag[16][4];
    {
        int aRow = w * 16 + (lane & 7) + ((lane >> 3) & 1) * 8;
        int aK = (lane >> 4) * 8;
        unsigned aA = sptr(sReg) + ((aRow * 264 + aK) << 1);
        #pragma unroll
        for (int kt = 0; kt < 16; ++kt) ldsm4(Afrag[kt], aA + ((kt * 16) << 1));
    }
    __syncthreads();

    auto loadH = [&](int buf, int jc) {
        const __nv_bfloat16* bsrc = hbp + (long)jc * 64 * HDIM;
        #pragma unroll
        for (int q = 0; q < 8; ++q) {
            int idx = tid + q * 256;
            int r = idx >> 5, k8 = idx & 31;
            cpa16(sptr(&sBuf[buf][r * 264 + k8 * 8]), &bsrc[(long)r * HDIM + k8 * 8]);
        }
        cpcommit();
    };

    int bRowBase = (lane & 7) + ((lane >> 4)) * 8;
    int bK = ((lane >> 3) & 1) * 8;

    // early-stopped certification over NJC*64 columns
    int cntA = 0, cntB = 0;
    loadH(0, 0);
    for (int jc = 0; jc < NJC; ++jc) {
        cpwait<0>();
        __syncthreads();
        if (jc + 1 < NJC) loadH((jc + 1) & 1, jc + 1);
        unsigned bA0 = sptr(sBuf[jc & 1]) + ((bRowBase * 264 + bK) << 1);
        #pragma unroll
        for (int ntp = 0; ntp < 4; ++ntp) {
            float c0[4] = {0.f, 0.f, 0.f, 0.f};
            float c1[4] = {0.f, 0.f, 0.f, 0.f};
            unsigned ba = bA0 + ((ntp * 16 * 264) << 1);
            #pragma unroll
            for (int kt = 0; kt < 16; ++kt) {
                unsigned bf[4];
                ldsm4(bf, ba + ((kt * 16) << 1));
                mma16816bf(c0, Afrag[kt], &bf[0]);
                mma16816bf(c1, Afrag[kt], &bf[2]);
            }
            cntA += (c0[0] > TH_HI) + (c0[1] > TH_HI) + (c1[0] > TH_HI) + (c1[1] > TH_HI);
            cntB += (c0[2] > TH_HI) + (c0[3] > TH_HI) + (c1[2] > TH_HI) + (c1[3] > TH_HI);
        }
    }
    cntA += __shfl_xor_sync(0xffffffffu, cntA, 1);
    cntA += __shfl_xor_sync(0xffffffffu, cntA, 2);
    cntB += __shfl_xor_sync(0xffffffffu, cntB, 1);
    cntB += __shfl_xor_sync(0xffffffffu, cntB, 2);
    if ((lane & 3) == 0) {
        sCnt[w * 16 + gr] = cntA;
        sCnt[w * 16 + gr + 8] = cntB;
    }
    sCol[tid] = 0.f;   // adjustments only; base colsums come from fc_ln
    __syncthreads();

    // exact fallback for uncertain rows (statistically ~never taken)
    float battn = batt[n];
    for (int r = 0; r < 128; ++r) {
        if (sCnt[r] >= 308) continue;

        float* tI   = (float*)sReg;
        float* Srow = tI + 256;
        int*   hist = (int*)(Srow + 1024);
        int*   iv   = hist + 256;

        int gi = r0 + r;
        const float* hrow = g_h + base + (long)gi * HDIM;
        const float* aw = adjw + (long)n * HDIM * HDIM;

        {
            float acc = 0.f;
            for (int d = 0; d < 256; ++d) acc = fmaf(hrow[d], aw[d * 256 + tid], acc);
            tI[tid] = acc;
        }
        __syncthreads();
        for (int j = tid; j < 1024; j += 256) {
            const float* hj = g_h + base + (long)j * HDIM;
            float s = 0.f;
            for (int k = 0; k < 256; ++k) s = fmaf(tI[k], hj[k], s);
            Srow[j] = sigf(s);
        }
        if (tid == 0) iv[0] = 0;
        __syncthreads();
        {
            int c1 = 0;
            for (int j = tid; j < 1024; j += 256) c1 += (Srow[j] >= 1.0f);
            atomicAdd(&iv[0], c1);
        }
        __syncthreads();
        int cnt1 = iv[0];
        if (cnt1 >= 308) { __syncthreads(); continue; }

        if (w == 0) {
            unsigned prefix = 0; int rank = 716;
            for (int p = 3; p >= 0; --p) {
                for (int q2 = lane; q2 < 256; q2 += 32) hist[q2] = 0;
                __syncwarp();
                unsigned himask = (p == 3) ? 0u : (0xFFFFFFFFu << ((p + 1) * 8));
                for (int j = lane; j < 1024; j += 32) {
                    unsigned key = __float_as_uint(Srow[j]);
                    if ((key & himask) == prefix)
                        atomicAdd(&hist[(key >> (p * 8)) & 0xFF], 1);
                }
                __syncwarp();
                int part = 0;
                #pragma unroll
                for (int q2 = 0; q2 < 8; ++q2) part += hist[lane * 8 + q2];
                int scan = part;
                #pragma unroll
                for (int o = 1; o < 32; o <<= 1) {
                    int vv = __shfl_up_sync(0xffffffffu, scan, o);
                    if (lane >= o) scan += vv;
                }
                int excl = scan - part;
                unsigned vote = __ballot_sync(0xffffffffu, (excl <= rank) && (rank < excl + part));
                int srcl = __ffs(vote) - 1;
                int binsel = 0, nrank = 0;
                if (lane == srcl) {
                    int cum = excl;
                    #pragma unroll
                    for (int q2 = 0; q2 < 8; ++q2) {
                        int c = hist[lane * 8 + q2];
                        if (cum + c > rank) { binsel = lane * 8 + q2; nrank = rank - cum; break; }
                        cum += c;
                    }
                }
                binsel = __shfl_sync(0xffffffffu, binsel, srcl);
                rank   = __shfl_sync(0xffffffffu, nrank, srcl);
                prefix |= (unsigned)binsel << (p * 8);
                __syncwarp();
            }
            float v1 = __uint_as_float(prefix);
            int cnt = 0; unsigned mn = 0xFFFFFFFFu;
            for (int j = lane; j < 1024; j += 32) {
                unsigned key = __float_as_uint(Srow[j]);
                if (key <= prefix) cnt++; else mn = min(mn, key);
            }
            #pragma unroll
            for (int o = 16; o; o >>= 1) {
                cnt += __shfl_xor_sync(0xffffffffu, cnt, o);
                mn = min(mn, __shfl_xor_sync(0xffffffffu, mn, o));
            }
            float v2 = (cnt >= 718) ? v1 : __uint_as_float(mn);
            const float frac = (float)(0.7 * 1023.0 - 716.0);
            float delta = v1 + frac * (v2 - v1);

            float es = g_esrc[erow0 + gi];
            float m = -1e30f;
            for (int j = lane; j < 1024; j += 32) {
                if (Srow[j] > delta || j == gi) {
                    float x = es + g_edst[erow0 + j] + battn;
                    float e = x > 0.f ? x : 0.01f * x;
                    m = fmaxf(m, e);
                }
            }
            #pragma unroll
            for (int o = 16; o; o >>= 1) m = fmaxf(m, __shfl_xor_sync(0xffffffffu, m, o));
            float ssum = 0.f;
            for (int j = lane; j < 1024; j += 32) {
                if (Srow[j] > delta || j == gi) {
                    float x = es + g_edst[erow0 + j] + battn;
                    float e = x > 0.f ? x : 0.01f * x;
                    ssum += expf(e - m);
                }
            }
            ssum = wredsum(ssum);
            float inv = 1.f / ssum;
            for (int j = lane; j < 1024; j += 32) {
                bool msk = (Srow[j] > delta) || (j == gi);
                float aj = 0.f;
                if (msk) {
                    float x = es + g_edst[erow0 + j] + battn;
                    float e = x > 0.f ? x : 0.01f * x;
                    aj = expf(e - m) * inv;
                }
                Srow[j] = aj;
            }
        }
        __syncthreads();
        {
            float acc = 0.f;
            for (int j = 0; j < 1024; ++j)
                acc = fmaf(Srow[j], g_h[base + (long)j * HDIM + tid], acc);
            sCol[tid] += acc - hrow[tid];
        }
        __syncthreads();
    }

    g_adj[(nb * 8 + mb) * 256 + tid] = sCol[tid];
}

// ---------------- final: means -> 3 GEMMs -> LN -> d_out ----------------
__global__ void __launch_bounds__(256) final_kernel(
    const float* __restrict__ W0, const float* __restrict__ b0,
    const float* __restrict__ W1, const float* __restrict__ b1,
    const float* __restrict__ W2, const float* __restrict__ b2,
    const float* __restrict__ g0, const float* __restrict__ be0,
    const float* __restrict__ g1, const float* __restrict__ be1,
    const float* __restrict__ g2, const float* __restrict__ be2,
    float* __restrict__ out)
{
    __shared__ float vin[1024];
    __shared__ float red[40];
    int which = blockIdx.x, b = blockIdx.y, tid = threadIdx.x;
    int K = (which == 2) ? 1024 : 512;
    int hb2 = (which == 1) ? 2 : 0;

    for (int e = tid; e < K; e += 256) {
        int n = hb2 + (e >> 8), col = e & 255;
        const float* p = g_partial + ((long)(n * 16 + b) * 16) * 256 + col;
        const float* a = g_adj + ((long)(n * 16 + b) * 8) * 256 + col;
        float s = 0.f;
        #pragma unroll
        for (int ibk = 0; ibk < 16; ++ibk) s += p[ibk * 256];
        #pragma unroll
        for (int ibk = 0; ibk < 8; ++ibk) s += a[ibk * 256];
        vin[e] = s * (1.f / 1024.f);
    }
    __syncthreads();

    const float* W  = (which == 0) ? W0 : ((which == 1) ? W1 : W2);
    const float* bi = (which == 0) ? b0 : ((which == 1) ? b1 : b2);
    const float* g  = (which == 0) ? g0 : ((which == 1) ? g1 : g2);
    const float* be = (which == 0) ? be0 : ((which == 1) ? be1 : be2);

    float acc3[3];
    #pragma unroll
    for (int oi = 0; oi < 3; ++oi) {
        int o = tid + oi * 256;
        float a = bi[o];
        for (int k = 0; k < K; ++k) a = fmaf(vin[k], W[(long)k * OUTD + o], a);
        acc3[oi] = a;
    }

    float ls = acc3[0] + acc3[1] + acc3[2];
    ls = wredsum(ls);
    if ((tid & 31) == 0) red[tid >> 5] = ls;
    __syncthreads();
    if (tid == 0) {
        float s = 0.f;
        for (int q = 0; q < 8; ++q) s += red[q];
        red[32] = s * (1.f / 768.f);
    }
    __syncthreads();
    float mu = red[32];
    __syncthreads();
    float vv = 0.f;
    #pragma unroll
    for (int oi = 0; oi < 3; ++oi) { float d = acc3[oi] - mu; vv += d * d; }
    vv = wredsum(vv);
    if ((tid & 31) == 0) red[tid >> 5] = vv;
    __syncthreads();
    if (tid == 0) {
        float s = 0.f;
        for (int q = 0; q < 8; ++q) s += red[q];
        red[33] = s * (1.f / 768.f);
    }
    __syncthreads();
    float rstd = rsqrtf(red[33] + 1e-5f);
    #pragma unroll
    for (int oi = 0; oi < 3; ++oi) {
        int o = tid + oi * 256;
        out[(long)which * BB * OUTD + (long)b * OUTD + o] = (acc3[oi] - mu) * rstd * g[o] + be[o];
    }
}

// ---------------- launch ----------------
extern "C" void kernel_launch(void* const* d_in, const int* in_sizes, int n_in,
                              void* d_out, int out_size)
{
    const float* x    = (const float*)d_in[0];
    const float* Wfc  = (const float*)d_in[1];
    const float* bfc  = (const float*)d_in[2];
    const float* lng  = (const float*)d_in[3];
    const float* lnb  = (const float*)d_in[4];
    const float* adjw = (const float*)d_in[5];
    const float* Watt = (const float*)d_in[6];
    const float* batt = (const float*)d_in[7];
    const float* Wl = (const float*)d_in[8];  const float* bl = (const float*)d_in[9];
    const float* Ws = (const float*)d_in[10]; const float* bs = (const float*)d_in[11];
    const float* Wc = (const float*)d_in[12]; const float* bc = (const float*)d_in[13];
    const float* gl = (const float*)d_in[14]; const float* bel = (const float*)d_in[15];
    const float* gs = (const float*)d_in[16]; const float* bes = (const float*)d_in[17];
    const float* gc = (const float*)d_in[18]; const float* bec = (const float*)d_in[19];
    float* out = (float*)d_out;

    // 0) prep: fp16 x, fp16 W^T, bf16 adjw^T
    split_x_kernel<<<(BLROWS * DDIM) / 1024, 256>>>(x);
    split_W_kernel<<<dim3(DDIM / 32, HDIM / 32, NHEAD), dim3(32, 8)>>>(Wfc);
    adjwT_kernel<<<dim3(HDIM / 32, HDIM / 32, NHEAD), dim3(32, 8)>>>(adjw);

    // 1) fused h = LN(x@Wfc+bfc), 64x256 CTA tile, 2 CTAs/SM
    const int smemFC = 3 * (64 + 256) * 40 * 2;   // 76,800 B
    cudaFuncSetAttribute(fc_ln_kernel, cudaFuncAttributeMaxDynamicSharedMemorySize, smemFC);
    fc_ln_kernel<<<dim3(256, NHEAD), 256, smemFC>>>(bfc, lng, lnb, Watt);

    // 2) tb = hb @ adjw (bf16 tensor, pipelined)
    const int smemTB = 128 * 264 * 2;
    cudaFuncSetAttribute(tb_gemm_kernel, cudaFuncAttributeMaxDynamicSharedMemorySize, smemTB);
    tb_gemm_kernel<<<dim3(BLROWS / 128, NHEAD), 256, smemTB>>>();

    // 3) attention counting + fallback adjustments
    const int smemAT = 128 * 264 * 2 + 256 * 4 + 128 * 4 + 64;
    cudaFuncSetAttribute(attn_count_kernel, cudaFuncAttributeMaxDynamicSharedMemorySize, smemAT);
    attn_count_kernel<<<dim3(8, BB, NHEAD), 256, smemAT>>>(adjw, batt);

    // 4) finals
    final_kernel<<<dim3(3, BB), 256>>>(Wl, bl, Ws, bs, Wc, bc, gl, bel, gs, bes, gc, bec, out);
}

// round 17
// speedup vs baseline: 1.0951x; 1.0951x over previous
#include <cuda_runtime.h>
#include <cuda_bf16.h>
#include <cuda_fp16.h>
#include <math.h>
#include <stdint.h>

#define BB     16
#define LSEQ   1024
#define DDIM   768
#define HDIM   256
#define NHEAD  4
#define OUTD   768
#define BLROWS (BB*LSEQ)          // 16384
#define NJC    13                 // early-stop chunk count for certification

// ---------------- scratch (device globals; no allocation) ----------------
__device__ __nv_bfloat16 g_hb[(size_t)NHEAD * BLROWS * HDIM];     // bf16 h
__device__ __nv_bfloat16 g_tb[(size_t)NHEAD * BLROWS * HDIM];     // bf16 t
__device__ __nv_bfloat16 g_adjwT[(size_t)NHEAD * HDIM * HDIM];    // adjw^T bf16
__device__ __half g_xh[(size_t)BLROWS * DDIM];                    // fp16 x
__device__ __half g_WTh[(size_t)NHEAD * HDIM * DDIM];             // fp16 Wfc^T
__device__ float g_esrc[NHEAD * BLROWS];
__device__ float g_edst[NHEAD * BLROWS];
__device__ float g_partial[NHEAD * BB * 8 * HDIM];                // base colsums (from fc_ln)
__device__ float g_adj[NHEAD * BB * 8 * HDIM];                    // fallback adjustments (from attn)

// ---------------- helpers ----------------
__device__ __forceinline__ float wredsum(float v) {
    #pragma unroll
    for (int o = 16; o; o >>= 1) v += __shfl_xor_sync(0xffffffffu, v, o);
    return v;
}
__device__ __forceinline__ float sigf(float x) {
    if (x >= 0.f) { float z = expf(-x); return 1.f / (1.f + z); }
    float z = expf(x); return z / (1.f + z);
}
__device__ __forceinline__ void mma16816bf(float c[4], const unsigned a[4], const unsigned b[2]) {
    asm volatile("mma.sync.aligned.m16n8k16.row.col.f32.bf16.bf16.f32 "
        "{%0,%1,%2,%3}, {%4,%5,%6,%7}, {%8,%9}, {%0,%1,%2,%3};"
        : "+f"(c[0]), "+f"(c[1]), "+f"(c[2]), "+f"(c[3])
        : "r"(a[0]), "r"(a[1]), "r"(a[2]), "r"(a[3]), "r"(b[0]), "r"(b[1]));
}
__device__ __forceinline__ void mma16816f(float c[4], const unsigned a[4], const unsigned b[2]) {
    asm volatile("mma.sync.aligned.m16n8k16.row.col.f32.f16.f16.f32 "
        "{%0,%1,%2,%3}, {%4,%5,%6,%7}, {%8,%9}, {%0,%1,%2,%3};"
        : "+f"(c[0]), "+f"(c[1]), "+f"(c[2]), "+f"(c[3])
        : "r"(a[0]), "r"(a[1]), "r"(a[2]), "r"(a[3]), "r"(b[0]), "r"(b[1]));
}
__device__ __forceinline__ void ldsm4(unsigned r[4], unsigned addr) {
    asm volatile("ldmatrix.sync.aligned.m8n8.x4.shared.b16 {%0,%1,%2,%3}, [%4];"
        : "=r"(r[0]), "=r"(r[1]), "=r"(r[2]), "=r"(r[3]) : "r"(addr));
}
__device__ __forceinline__ unsigned sptr(const void* p) {
    return (unsigned)__cvta_generic_to_shared(p);
}
__device__ __forceinline__ void cpa16(unsigned dst, const void* src) {
    asm volatile("cp.async.cg.shared.global [%0], [%1], 16;" :: "r"(dst), "l"(src));
}
__device__ __forceinline__ void cpcommit() { asm volatile("cp.async.commit_group;"); }
template<int N> __device__ __forceinline__ void cpwait() {
    asm volatile("cp.async.wait_group %0;" :: "n"(N));
}

// ---------------- prep: x -> fp16 ----------------
__global__ void split_x_kernel(const float* __restrict__ x)
{
    long i = (long)blockIdx.x * 1024 + threadIdx.x * 4;
    float4 v = *(const float4*)(x + i);
    *(__half2*)&g_xh[i]     = __floats2half2_rn(v.x, v.y);
    *(__half2*)&g_xh[i + 2] = __floats2half2_rn(v.z, v.w);
}

// ---------------- prep: Wfc^T fp16, tiled transpose ----------------
__global__ void split_W_kernel(const float* __restrict__ Wfc)
{
    __shared__ float t[32][33];
    int d0 = blockIdx.x * 32, e0 = blockIdx.y * 32, n = blockIdx.z;
    int tx = threadIdx.x, ty = threadIdx.y;
    #pragma unroll
    for (int r = 0; r < 4; ++r) {
        int d = d0 + ty * 4 + r;
        t[ty * 4 + r][tx] = Wfc[((long)n * DDIM + d) * HDIM + e0 + tx];
    }
    __syncthreads();
    #pragma unroll
    for (int r = 0; r < 4; ++r) {
        int e = e0 + ty * 4 + r;
        g_WTh[((long)n * HDIM + e) * DDIM + d0 + tx] = __float2half(t[tx][ty * 4 + r]);
    }
}

// ---------------- prep: adjw^T bf16, tiled transpose ----------------
__global__ void adjwT_kernel(const float* __restrict__ adjw)
{
    __shared__ float t[32][33];
    int d0 = blockIdx.x * 32, e0 = blockIdx.y * 32, n = blockIdx.z;
    int tx = threadIdx.x, ty = threadIdx.y;
    #pragma unroll
    for (int r = 0; r < 4; ++r) {
        int d = d0 + ty * 4 + r;
        t[ty * 4 + r][tx] = adjw[((long)n * HDIM + d) * HDIM + e0 + tx];
    }
    __syncthreads();
    #pragma unroll
    for (int r = 0; r < 4; ++r) {
        int e = e0 + ty * 4 + r;
        g_adjwT[((long)n * HDIM + e) * HDIM + d0 + tx] = __float2bfloat16(t[tx][ty * 4 + r]);
    }
}

// ---------------- fused stage 1: h = LN(x @ Wfc + bfc) ----------------
// grid (128 mblk, NHEAD); block 512 = 16 warps (4x4); warp tile 32x64
// Register-resident epilogue; writes only bf16 h (no fp32 h array).
__global__ void __launch_bounds__(512, 1) fc_ln_kernel(
    const float* __restrict__ bfc, const float* __restrict__ lng,
    const float* __restrict__ lnb, const float* __restrict__ Watt)
{
    extern __shared__ char smraw[];
    __half* sA = (__half*)smraw;                       // 3 * 128*40
    __half* sB = sA + 3 * 128 * 40;                    // 3 * 256*40
    // epilogue overlay (mainloop smem dead): tiny stat buffers
    float* rs     = (float*)smraw;                     // 128*4
    float* rq     = rs + 512;                          // 128*4
    float* esb    = rq + 512;                          // 128*4
    float* edb    = esb + 512;                         // 128*4
    float* colbuf = edb + 512;                         // 4*256

    int mblk = blockIdx.x, head = blockIdx.y;
    int tid = threadIdx.x, lane = tid & 31, w = tid >> 5;
    int wr = w >> 2, wc = w & 3;        // 4x4 warp grid

    const __half* Ag = g_xh + (long)mblk * 128 * DDIM;
    const __half* Bg = g_WTh + (long)head * HDIM * DDIM;

    float c[2][8][4];
    #pragma unroll
    for (int i = 0; i < 2; ++i)
        #pragma unroll
        for (int j = 0; j < 8; ++j)
            #pragma unroll
            for (int q = 0; q < 4; ++q) c[i][j][q] = 0.f;

    int aRow = wr * 32 + (lane & 7) + ((lane >> 3) & 1) * 8;
    int aK   = (lane >> 4) * 8;
    int bRow = wc * 64 + (lane & 7) + ((lane >> 4)) * 8;
    int bK   = ((lane >> 3) & 1) * 8;
    unsigned aAbase[3], bAbase[3];
    #pragma unroll
    for (int bb2 = 0; bb2 < 3; ++bb2) {
        aAbase[bb2] = sptr(sA + bb2 * 128 * 40) + ((aRow * 40 + aK) << 1);
        bAbase[bb2] = sptr(sB + bb2 * 256 * 40) + ((bRow * 40 + bK) << 1);
    }

    auto loadChunk = [&](int buf, int k0) {
        {
            int row = tid >> 2, part = tid & 3;
            cpa16(sptr(sA + buf * 128 * 40 + row * 40 + part * 8),
                  &Ag[(long)row * DDIM + k0 + part * 8]);
        }
        #pragma unroll
        for (int q = 0; q < 2; ++q) {
            int idx = tid + q * 512;
            int row = idx >> 2, part = idx & 3;
            cpa16(sptr(sB + buf * 256 * 40 + row * 40 + part * 8),
                  &Bg[(long)row * DDIM + k0 + part * 8]);
        }
        cpcommit();
    };

    loadChunk(0, 0);
    loadChunk(1, 32);
    int buf = 0;
    for (int kc = 0; kc < 24; ++kc) {
        cpwait<1>();
        __syncthreads();
        if (kc + 2 < 24) loadChunk((buf + 2) % 3, (kc + 2) * 32);
        #pragma unroll
        for (int ks = 0; ks < 32; ks += 16) {
            unsigned ah[2][4], bh[4][4];
            #pragma unroll
            for (int mt = 0; mt < 2; ++mt)
                ldsm4(ah[mt], aAbase[buf] + ((mt * 16 * 40 + ks) << 1));
            #pragma unroll
            for (int p = 0; p < 4; ++p)
                ldsm4(bh[p], bAbase[buf] + ((p * 16 * 40 + ks) << 1));
            #pragma unroll
            for (int mt = 0; mt < 2; ++mt)
                #pragma unroll
                for (int nt = 0; nt < 8; ++nt)
                    mma16816f(c[mt][nt], ah[mt], &bh[nt >> 1][(nt & 1) * 2]);
        }
        buf = (buf + 1) % 3;
    }
    __syncthreads();   // mainloop smem dead; overlay stats

    // ---- bias add (registers) ----
    const float* bias = bfc + head * HDIM;
    #pragma unroll
    for (int mt = 0; mt < 2; ++mt)
        #pragma unroll
        for (int nt = 0; nt < 8; ++nt) {
            int col = wc * 64 + nt * 8 + (lane & 3) * 2;
            float b0 = bias[col], b1 = bias[col + 1];
            c[mt][nt][0] += b0; c[mt][nt][1] += b1;
            c[mt][nt][2] += b0; c[mt][nt][3] += b1;
        }

    int rowbase = wr * 32 + (lane >> 2);
    int myrow[4];
    #pragma unroll
    for (int ri = 0; ri < 4; ++ri) myrow[ri] = rowbase + (ri >> 1) * 16 + (ri & 1) * 8;

    // ---- pass 1: row sums ----
    {
        float srow[4] = {0.f, 0.f, 0.f, 0.f};
        #pragma unroll
        for (int mt = 0; mt < 2; ++mt)
            #pragma unroll
            for (int nt = 0; nt < 8; ++nt) {
                srow[mt * 2 + 0] += c[mt][nt][0] + c[mt][nt][1];
                srow[mt * 2 + 1] += c[mt][nt][2] + c[mt][nt][3];
            }
        #pragma unroll
        for (int ri = 0; ri < 4; ++ri) {
            srow[ri] += __shfl_xor_sync(0xffffffffu, srow[ri], 1);
            srow[ri] += __shfl_xor_sync(0xffffffffu, srow[ri], 2);
        }
        if ((lane & 3) == 0) {
            #pragma unroll
            for (int ri = 0; ri < 4; ++ri) rs[myrow[ri] * 4 + wc] = srow[ri];
        }
    }
    __syncthreads();
    float mu[4];
    #pragma unroll
    for (int ri = 0; ri < 4; ++ri)
        mu[ri] = (rs[myrow[ri] * 4 + 0] + rs[myrow[ri] * 4 + 1] +
                  rs[myrow[ri] * 4 + 2] + rs[myrow[ri] * 4 + 3]) * (1.f / 256.f);

    // ---- pass 2: row sumsq of (v - mu) ----
    {
        float qrow[4] = {0.f, 0.f, 0.f, 0.f};
        #pragma unroll
        for (int mt = 0; mt < 2; ++mt)
            #pragma unroll
            for (int nt = 0; nt < 8; ++nt) {
                float d0 = c[mt][nt][0] - mu[mt * 2], d1 = c[mt][nt][1] - mu[mt * 2];
                float d2 = c[mt][nt][2] - mu[mt * 2 + 1], d3 = c[mt][nt][3] - mu[mt * 2 + 1];
                qrow[mt * 2 + 0] += d0 * d0 + d1 * d1;
                qrow[mt * 2 + 1] += d2 * d2 + d3 * d3;
            }
        #pragma unroll
        for (int ri = 0; ri < 4; ++ri) {
            qrow[ri] += __shfl_xor_sync(0xffffffffu, qrow[ri], 1);
            qrow[ri] += __shfl_xor_sync(0xffffffffu, qrow[ri], 2);
        }
        if ((lane & 3) == 0) {
            #pragma unroll
            for (int ri = 0; ri < 4; ++ri) rq[myrow[ri] * 4 + wc] = qrow[ri];
        }
    }
    __syncthreads();
    float rstd[4];
    #pragma unroll
    for (int ri = 0; ri < 4; ++ri) {
        float s2 = rq[myrow[ri] * 4 + 0] + rq[myrow[ri] * 4 + 1] +
                   rq[myrow[ri] * 4 + 2] + rq[myrow[ri] * 4 + 3];
        rstd[ri] = rsqrtf(s2 * (1.f / 256.f) + 1e-5f);
    }

    // ---- normalize, write hb, accumulate dots + colsums ----
    const float* gzp = lng + head * HDIM;
    const float* bzp = lnb + head * HDIM;
    const float* wsp = Watt + head * 2 * HDIM;
    const float* wdp = wsp + HDIM;
    long growbase = (long)head * BLROWS + (long)mblk * 128;

    float a1[4] = {0.f, 0.f, 0.f, 0.f}, a2[4] = {0.f, 0.f, 0.f, 0.f};
    float csum[16];
    #pragma unroll
    for (int q = 0; q < 16; ++q) csum[q] = 0.f;

    #pragma unroll
    for (int mt = 0; mt < 2; ++mt)
        #pragma unroll
        for (int nt = 0; nt < 8; ++nt) {
            int col = wc * 64 + nt * 8 + (lane & 3) * 2;
            float gz0 = gzp[col], gz1 = gzp[col + 1];
            float bz0 = bzp[col], bz1 = bzp[col + 1];
            float ws0 = wsp[col], ws1 = wsp[col + 1];
            float wd0 = wdp[col], wd1 = wdp[col + 1];
            int riA = mt * 2, riB = mt * 2 + 1;
            float o0 = (c[mt][nt][0] - mu[riA]) * rstd[riA] * gz0 + bz0;
            float o1 = (c[mt][nt][1] - mu[riA]) * rstd[riA] * gz1 + bz1;
            float o2 = (c[mt][nt][2] - mu[riB]) * rstd[riB] * gz0 + bz0;
            float o3 = (c[mt][nt][3] - mu[riB]) * rstd[riB] * gz1 + bz1;

            long rA = growbase + myrow[riA];
            long rB = growbase + myrow[riB];
            *(__nv_bfloat162*)&g_hb[rA * HDIM + col] = __floats2bfloat162_rn(o0, o1);
            *(__nv_bfloat162*)&g_hb[rB * HDIM + col] = __floats2bfloat162_rn(o2, o3);

            a1[riA] = fmaf(o0, ws0, fmaf(o1, ws1, a1[riA]));
            a2[riA] = fmaf(o0, wd0, fmaf(o1, wd1, a2[riA]));
            a1[riB] = fmaf(o2, ws0, fmaf(o3, ws1, a1[riB]));
            a2[riB] = fmaf(o2, wd0, fmaf(o3, wd1, a2[riB]));

            csum[nt * 2 + 0] += o0 + o2;
            csum[nt * 2 + 1] += o1 + o3;
        }

    #pragma unroll
    for (int ri = 0; ri < 4; ++ri) {
        a1[ri] += __shfl_xor_sync(0xffffffffu, a1[ri], 1);
        a1[ri] += __shfl_xor_sync(0xffffffffu, a1[ri], 2);
        a2[ri] += __shfl_xor_sync(0xffffffffu, a2[ri], 1);
        a2[ri] += __shfl_xor_sync(0xffffffffu, a2[ri], 2);
    }
    if ((lane & 3) == 0) {
        #pragma unroll
        for (int ri = 0; ri < 4; ++ri) {
            esb[myrow[ri] * 4 + wc] = a1[ri];
            edb[myrow[ri] * 4 + wc] = a2[ri];
        }
    }

    #pragma unroll
    for (int q = 0; q < 16; ++q) {
        csum[q] += __shfl_xor_sync(0xffffffffu, csum[q], 4);
        csum[q] += __shfl_xor_sync(0xffffffffu, csum[q], 8);
        csum[q] += __shfl_xor_sync(0xffffffffu, csum[q], 16);
    }
    if (lane < 4) {
        #pragma unroll
        for (int nt = 0; nt < 8; ++nt) {
            int col = wc * 64 + nt * 8 + lane * 2;
            colbuf[wr * 256 + col]     = csum[nt * 2 + 0];
            colbuf[wr * 256 + col + 1] = csum[nt * 2 + 1];
        }
    }
    __syncthreads();

    if (tid < 128) {
        long grow = growbase + tid;
        g_esrc[grow] = esb[tid * 4 + 0] + esb[tid * 4 + 1] + esb[tid * 4 + 2] + esb[tid * 4 + 3];
        g_edst[grow] = edb[tid * 4 + 0] + edb[tid * 4 + 1] + edb[tid * 4 + 2] + edb[tid * 4 + 3];
    } else if (tid < 384) {
        int colx = tid - 128;
        float s = colbuf[colx] + colbuf[256 + colx] + colbuf[512 + colx] + colbuf[768 + colx];
        int b = mblk >> 3, mb = mblk & 7;
        g_partial[((long)(head * 16 + b) * 8 + mb) * 256 + colx] = s;
    }
}

// ---------------- tb = hb @ adjw (bf16 tensor, pipelined, smem overlay) ----
__global__ void __launch_bounds__(256, 2) tb_gemm_kernel()
{
    extern __shared__ char smraw[];
    __nv_bfloat16* sReg = (__nv_bfloat16*)smraw;     // 128*264
    __nv_bfloat16* sBuf[2] = { sReg, sReg + 64 * 264 };

    int mb = blockIdx.x, n = blockIdx.y;
    int tid = threadIdx.x, lane = tid & 31, w = tid >> 5;
    int gr = lane >> 2, qp = lane & 3;
    long rbase = (long)n * BLROWS + (long)mb * 128;
    const __nv_bfloat16* asrc = g_hb + rbase * HDIM;

    for (int idx = tid; idx < 128 * 32; idx += 256) {
        int r = idx >> 5, k8 = idx & 31;
        *(float4*)&sReg[r * 264 + k8 * 8] = *(const float4*)&asrc[(long)r * HDIM + k8 * 8];
    }
    __syncthreads();

    unsigned Afrag[16][4];
    {
        int aRow = w * 16 + (lane & 7) + ((lane >> 3) & 1) * 8;
        int aK = (lane >> 4) * 8;
        unsigned aA = sptr(sReg) + ((aRow * 264 + aK) << 1);
        #pragma unroll
        for (int kt = 0; kt < 16; ++kt) ldsm4(Afrag[kt], aA + ((kt * 16) << 1));
    }
    __syncthreads();

    auto loadB = [&](int buf, int ec) {
        const __nv_bfloat16* bsrc = g_adjwT + ((long)n * HDIM + ec * 64) * HDIM;
        #pragma unroll
        for (int q = 0; q < 8; ++q) {
            int idx = tid + q * 256;
            int r = idx >> 5, k8 = idx & 31;
            cpa16(sptr(&sBuf[buf][r * 264 + k8 * 8]), &bsrc[(long)r * HDIM + k8 * 8]);
        }
        cpcommit();
    };

    int bRowBase = (lane & 7) + ((lane >> 4)) * 8;
    int bK = ((lane >> 3) & 1) * 8;

    __nv_bfloat16* outp = g_tb + rbase * HDIM;
    loadB(0, 0);
    for (int ec = 0; ec < 4; ++ec) {
        cpwait<0>();
        __syncthreads();
        if (ec + 1 < 4) loadB((ec + 1) & 1, ec + 1);
        unsigned bA0 = sptr(sBuf[ec & 1]) + ((bRowBase * 264 + bK) << 1);
        #pragma unroll
        for (int ntp = 0; ntp < 4; ++ntp) {
            float c0[4] = {0.f, 0.f, 0.f, 0.f};
            float c1[4] = {0.f, 0.f, 0.f, 0.f};
            unsigned ba = bA0 + ((ntp * 16 * 264) << 1);
            #pragma unroll
            for (int kt = 0; kt < 16; ++kt) {
                unsigned bf[4];
                ldsm4(bf, ba + ((kt * 16) << 1));
                mma16816bf(c0, Afrag[kt], &bf[0]);
                mma16816bf(c1, Afrag[kt], &bf[2]);
            }
            int row = w * 16 + gr;
            int col = ec * 64 + ntp * 16 + qp * 2;
            *(__nv_bfloat162*)&outp[(long)row * HDIM + col] = __floats2bfloat162_rn(c0[0], c0[1]);
            *(__nv_bfloat162*)&outp[(long)(row + 8) * HDIM + col] = __floats2bfloat162_rn(c0[2], c0[3]);
            *(__nv_bfloat162*)&outp[(long)row * HDIM + col + 8] = __floats2bfloat162_rn(c1[0], c1[1]);
            *(__nv_bfloat162*)&outp[(long)(row + 8) * HDIM + col + 8] = __floats2bfloat162_rn(c1[2], c1[3]);
        }
    }
}

// ---------------- attention: tensor-core counting + exact fallback ------
#define TH_HI 33.4f
__global__ void __launch_bounds__(256, 2) attn_count_kernel(
    const float* __restrict__ adjw, const float* __restrict__ batt)
{
    extern __shared__ char smraw[];
    __nv_bfloat16* sReg = (__nv_bfloat16*)smraw;     // 128*264 overlay region
    __nv_bfloat16* sBuf[2] = { sReg, sReg + 64 * 264 };
    float* sCol = (float*)(sReg + 128 * 264);        // 256
    int*   sCnt = (int*)(sCol + 256);                // 128

    int mb = blockIdx.x, b = blockIdx.y, n = blockIdx.z;
    int tid = threadIdx.x, lane = tid & 31, w = tid >> 5;
    int gr = lane >> 2;
    long nb = (long)(n * 16 + b);
    long base = nb * LSEQ * HDIM;
    int r0 = mb * 128;
    int erow0 = n * BLROWS + b * LSEQ;
    const __nv_bfloat16* hbp = g_hb + base;
    const __nv_bfloat16* tbp = g_tb + base + (long)r0 * HDIM;

    for (int idx = tid; idx < 128 * 32; idx += 256) {
        int r = idx >> 5, k8 = idx & 31;
        *(float4*)&sReg[r * 264 + k8 * 8] = *(const float4*)&tbp[(long)r * HDIM + k8 * 8];
    }
    __syncthreads();

    unsigned Afrag[16][4];
    {
        int aRow = w * 16 + (lane & 7) + ((lane >> 3) & 1) * 8;
        int aK = (lane >> 4) * 8;
        unsigned aA = sptr(sReg) + ((aRow * 264 + aK) << 1);
        #pragma unroll
        for (int kt = 0; kt < 16; ++kt) ldsm4(Afrag[kt], aA + ((kt * 16) << 1));
    }
    __syncthreads();

    auto loadH = [&](int buf, int jc) {
        const __nv_bfloat16* bsrc = hbp + (long)jc * 64 * HDIM;
        #pragma unroll
        for (int q = 0; q < 8; ++q) {
            int idx = tid + q * 256;
            int r = idx >> 5, k8 = idx & 31;
            cpa16(sptr(&sBuf[buf][r * 264 + k8 * 8]), &bsrc[(long)r * HDIM + k8 * 8]);
        }
        cpcommit();
    };

    int bRowBase = (lane & 7) + ((lane >> 4)) * 8;
    int bK = ((lane >> 3) & 1) * 8;

    // early-stopped certification over NJC*64 columns
    int cntA = 0, cntB = 0;
    loadH(0, 0);
    for (int jc = 0; jc < NJC; ++jc) {
        cpwait<0>();
        __syncthreads();
        if (jc + 1 < NJC) loadH((jc + 1) & 1, jc + 1);
        unsigned bA0 = sptr(sBuf[jc & 1]) + ((bRowBase * 264 + bK) << 1);
        #pragma unroll
        for (int ntp = 0; ntp < 4; ++ntp) {
            float c0[4] = {0.f, 0.f, 0.f, 0.f};
            float c1[4] = {0.f, 0.f, 0.f, 0.f};
            unsigned ba = bA0 + ((ntp * 16 * 264) << 1);
            #pragma unroll
            for (int kt = 0; kt < 16; ++kt) {
                unsigned bf[4];
                ldsm4(bf, ba + ((kt * 16) << 1));
                mma16816bf(c0, Afrag[kt], &bf[0]);
                mma16816bf(c1, Afrag[kt], &bf[2]);
            }
            cntA += (c0[0] > TH_HI) + (c0[1] > TH_HI) + (c1[0] > TH_HI) + (c1[1] > TH_HI);
            cntB += (c0[2] > TH_HI) + (c0[3] > TH_HI) + (c1[2] > TH_HI) + (c1[3] > TH_HI);
        }
    }
    cntA += __shfl_xor_sync(0xffffffffu, cntA, 1);
    cntA += __shfl_xor_sync(0xffffffffu, cntA, 2);
    cntB += __shfl_xor_sync(0xffffffffu, cntB, 1);
    cntB += __shfl_xor_sync(0xffffffffu, cntB, 2);
    if ((lane & 3) == 0) {
        sCnt[w * 16 + gr] = cntA;
        sCnt[w * 16 + gr + 8] = cntB;
    }
    sCol[tid] = 0.f;   // adjustments only; base colsums come from fc_ln
    __syncthreads();

    // exact fallback for uncertain rows (statistically ~never taken; uses bf16 h)
    float battn = batt[n];
    for (int r = 0; r < 128; ++r) {
        if (sCnt[r] >= 308) continue;

        float* tI   = (float*)sReg;
        float* Srow = tI + 256;
        int*   hist = (int*)(Srow + 1024);
        int*   iv   = hist + 256;

        int gi = r0 + r;
        const __nv_bfloat16* hrow = g_hb + base + (long)gi * HDIM;
        const float* aw = adjw + (long)n * HDIM * HDIM;

        {
            float acc = 0.f;
            for (int d = 0; d < 256; ++d)
                acc = fmaf(__bfloat162float(hrow[d]), aw[d * 256 + tid], acc);
            tI[tid] = acc;
        }
        __syncthreads();
        for (int j = tid; j < 1024; j += 256) {
            const __nv_bfloat16* hj = g_hb + base + (long)j * HDIM;
            float s = 0.f;
            for (int k = 0; k < 256; ++k) s = fmaf(tI[k], __bfloat162float(hj[k]), s);
            Srow[j] = sigf(s);
        }
        if (tid == 0) iv[0] = 0;
        __syncthreads();
        {
            int c1 = 0;
            for (int j = tid; j < 1024; j += 256) c1 += (Srow[j] >= 1.0f);
            atomicAdd(&iv[0], c1);
        }
        __syncthreads();
        int cnt1 = iv[0];
        if (cnt1 >= 308) { __syncthreads(); continue; }

        if (w == 0) {
            unsigned prefix = 0; int rank = 716;
            for (int p = 3; p >= 0; --p) {
                for (int q2 = lane; q2 < 256; q2 += 32) hist[q2] = 0;
                __syncwarp();
                unsigned himask = (p == 3) ? 0u : (0xFFFFFFFFu << ((p + 1) * 8));
                for (int j = lane; j < 1024; j += 32) {
                    unsigned key = __float_as_uint(Srow[j]);
                    if ((key & himask) == prefix)
                        atomicAdd(&hist[(key >> (p * 8)) & 0xFF], 1);
                }
                __syncwarp();
                int part = 0;
                #pragma unroll
                for (int q2 = 0; q2 < 8; ++q2) part += hist[lane * 8 + q2];
                int scan = part;
                #pragma unroll
                for (int o = 1; o < 32; o <<= 1) {
                    int vv = __shfl_up_sync(0xffffffffu, scan, o);
                    if (lane >= o) scan += vv;
                }
                int excl = scan - part;
                unsigned vote = __ballot_sync(0xffffffffu, (excl <= rank) && (rank < excl + part));
                int srcl = __ffs(vote) - 1;
                int binsel = 0, nrank = 0;
                if (lane == srcl) {
                    int cum = excl;
                    #pragma unroll
                    for (int q2 = 0; q2 < 8; ++q2) {
                        int c = hist[lane * 8 + q2];
                        if (cum + c > rank) { binsel = lane * 8 + q2; nrank = rank - cum; break; }
                        cum += c;
                    }
                }
                binsel = __shfl_sync(0xffffffffu, binsel, srcl);
                rank   = __shfl_sync(0xffffffffu, nrank, srcl);
                prefix |= (unsigned)binsel << (p * 8);
                __syncwarp();
            }
            float v1 = __uint_as_float(prefix);
            int cnt = 0; unsigned mn = 0xFFFFFFFFu;
            for (int j = lane; j < 1024; j += 32) {
                unsigned key = __float_as_uint(Srow[j]);
                if (key <= prefix) cnt++; else mn = min(mn, key);
            }
            #pragma unroll
            for (int o = 16; o; o >>= 1) {
                cnt += __shfl_xor_sync(0xffffffffu, cnt, o);
                mn = min(mn, __shfl_xor_sync(0xffffffffu, mn, o));
            }
            float v2 = (cnt >= 718) ? v1 : __uint_as_float(mn);
            const float frac = (float)(0.7 * 1023.0 - 716.0);
            float delta = v1 + frac * (v2 - v1);

            float es = g_esrc[erow0 + gi];
            float m = -1e30f;
            for (int j = lane; j < 1024; j += 32) {
                if (Srow[j] > delta || j == gi) {
                    float x = es + g_edst[erow0 + j] + battn;
                    float e = x > 0.f ? x : 0.01f * x;
                    m = fmaxf(m, e);
                }
            }
            #pragma unroll
            for (int o = 16; o; o >>= 1) m = fmaxf(m, __shfl_xor_sync(0xffffffffu, m, o));
            float ssum = 0.f;
            for (int j = lane; j < 1024; j += 32) {
                if (Srow[j] > delta || j == gi) {
                    float x = es + g_edst[erow0 + j] + battn;
                    float e = x > 0.f ? x : 0.01f * x;
                    ssum += expf(e - m);
                }
            }
            ssum = wredsum(ssum);
            float inv = 1.f / ssum;
            for (int j = lane; j < 1024; j += 32) {
                bool msk = (Srow[j] > delta) || (j == gi);
                float aj = 0.f;
                if (msk) {
                    float x = es + g_edst[erow0 + j] + battn;
                    float e = x > 0.f ? x : 0.01f * x;
                    aj = expf(e - m) * inv;
                }
                Srow[j] = aj;
            }
        }
        __syncthreads();
        {
            float acc = 0.f;
            for (int j = 0; j < 1024; ++j)
                acc = fmaf(Srow[j], __bfloat162float(g_hb[base + (long)j * HDIM + tid]), acc);
            sCol[tid] += acc - __bfloat162float(hrow[tid]);
        }
        __syncthreads();
    }

    g_adj[(nb * 8 + mb) * 256 + tid] = sCol[tid];
}

// ---------------- final: means -> 3 GEMMs -> LN -> d_out ----------------
__global__ void __launch_bounds__(256) final_kernel(
    const float* __restrict__ W0, const float* __restrict__ b0,
    const float* __restrict__ W1, const float* __restrict__ b1,
    const float* __restrict__ W2, const float* __restrict__ b2,
    const float* __restrict__ g0, const float* __restrict__ be0,
    const float* __restrict__ g1, const float* __restrict__ be1,
    const float* __restrict__ g2, const float* __restrict__ be2,
    float* __restrict__ out)
{
    __shared__ float vin[1024];
    __shared__ float red[40];
    int which = blockIdx.x, b = blockIdx.y, tid = threadIdx.x;
    int K = (which == 2) ? 1024 : 512;
    int hb2 = (which == 1) ? 2 : 0;

    for (int e = tid; e < K; e += 256) {
        int n = hb2 + (e >> 8), col = e & 255;
        long sb = ((long)(n * 16 + b) * 8) * 256 + col;
        const float* p = g_partial + sb;
        const float* a = g_adj + sb;
        float s = 0.f;
        #pragma unroll
        for (int ibk = 0; ibk < 8; ++ibk) s += p[ibk * 256] + a[ibk * 256];
        vin[e] = s * (1.f / 1024.f);
    }
    __syncthreads();

    const float* W  = (which == 0) ? W0 : ((which == 1) ? W1 : W2);
    const float* bi = (which == 0) ? b0 : ((which == 1) ? b1 : b2);
    const float* g  = (which == 0) ? g0 : ((which == 1) ? g1 : g2);
    const float* be = (which == 0) ? be0 : ((which == 1) ? be1 : be2);

    float acc3[3];
    #pragma unroll
    for (int oi = 0; oi < 3; ++oi) {
        int o = tid + oi * 256;
        float a = bi[o];
        for (int k = 0; k < K; ++k) a = fmaf(vin[k], W[(long)k * OUTD + o], a);
        acc3[oi] = a;
    }

    float ls = acc3[0] + acc3[1] + acc3[2];
    ls = wredsum(ls);
    if ((tid & 31) == 0) red[tid >> 5] = ls;
    __syncthreads();
    if (tid == 0) {
        float s = 0.f;
        for (int q = 0; q < 8; ++q) s += red[q];
        red[32] = s * (1.f / 768.f);
    }
    __syncthreads();
    float mu = red[32];
    __syncthreads();
    float vv = 0.f;
    #pragma unroll
    for (int oi = 0; oi < 3; ++oi) { float d = acc3[oi] - mu; vv += d * d; }
    vv = wredsum(vv);
    if ((tid & 31) == 0) red[tid >> 5] = vv;
    __syncthreads();
    if (tid == 0) {
        float s = 0.f;
        for (int q = 0; q < 8; ++q) s += red[q];
        red[33] = s * (1.f / 768.f);
    }
    __syncthreads();
    float rstd = rsqrtf(red[33] + 1e-5f);
    #pragma unroll
    for (int oi = 0; oi < 3; ++oi) {
        int o = tid + oi * 256;
        out[(long)which * BB * OUTD + (long)b * OUTD + o] = (acc3[oi] - mu) * rstd * g[o] + be[o];
    }
}

// ---------------- launch ----------------
extern "C" void kernel_launch(void* const* d_in, const int* in_sizes, int n_in,
                              void* d_out, int out_size)
{
    const float* x    = (const float*)d_in[0];
    const float* Wfc  = (const float*)d_in[1];
    const float* bfc  = (const float*)d_in[2];
    const float* lng  = (const float*)d_in[3];
    const float* lnb  = (const float*)d_in[4];
    const float* adjw = (const float*)d_in[5];
    const float* Watt = (const float*)d_in[6];
    const float* batt = (const float*)d_in[7];
    const float* Wl = (const float*)d_in[8];  const float* bl = (const float*)d_in[9];
    const float* Ws = (const float*)d_in[10]; const float* bs = (const float*)d_in[11];
    const float* Wc = (const float*)d_in[12]; const float* bc = (const float*)d_in[13];
    const float* gl = (const float*)d_in[14]; const float* bel = (const float*)d_in[15];
    const float* gs = (const float*)d_in[16]; const float* bes = (const float*)d_in[17];
    const float* gc = (const float*)d_in[18]; const float* bec = (const float*)d_in[19];
    float* out = (float*)d_out;

    // 0) prep: fp16 x, fp16 W^T, bf16 adjw^T
    split_x_kernel<<<(BLROWS * DDIM) / 1024, 256>>>(x);
    split_W_kernel<<<dim3(DDIM / 32, HDIM / 32, NHEAD), dim3(32, 8)>>>(Wfc);
    adjwT_kernel<<<dim3(HDIM / 32, HDIM / 32, NHEAD), dim3(32, 8)>>>(adjw);

    // 1) fused h = LN(x@Wfc+bfc), register epilogue, bf16-only h output
    const int smemFC = 3 * 128 * 40 * 2 + 3 * 256 * 40 * 2;   // 92,160 B mainloop
    cudaFuncSetAttribute(fc_ln_kernel, cudaFuncAttributeMaxDynamicSharedMemorySize, smemFC);
    fc_ln_kernel<<<dim3(128, NHEAD), 512, smemFC>>>(bfc, lng, lnb, Watt);

    // 2) tb = hb @ adjw (bf16 tensor, pipelined)
    const int smemTB = 128 * 264 * 2;
    cudaFuncSetAttribute(tb_gemm_kernel, cudaFuncAttributeMaxDynamicSharedMemorySize, smemTB);
    tb_gemm_kernel<<<dim3(BLROWS / 128, NHEAD), 256, smemTB>>>();

    // 3) attention counting + fallback adjustments
    const int smemAT = 128 * 264 * 2 + 256 * 4 + 128 * 4 + 64;
    cudaFuncSetAttribute(attn_count_kernel, cudaFuncAttributeMaxDynamicSharedMemorySize, smemAT);
    attn_count_kernel<<<dim3(8, BB, NHEAD), 256, smemAT>>>(adjw, batt);

    // 4) finals
    final_kernel<<<dim3(3, BB), 256>>>(Wl, bl, Ws, bs, Wc, bc, gl, bel, gs, bes, gc, bec, out);
}